// round 3
// baseline (speedup 1.0000x reference)
#include <cuda_runtime.h>

#define Hh   51
#define H4   204
#define KP   52          // padded K dim (13 * float4)
#define NCH  13
#define Tt   2048
#define FUT  64
#define OTot 2112
#define Bt   8192
#define BPC  64          // batch elements per CTA
#define TPB  256         // (BPC/2) * 8 lanes
#define NPOS 7

typedef unsigned long long u64;

__device__ __forceinline__ void fma2(u64 &d, u64 a, u64 b){
    asm("fma.rn.f32x2 %0, %1, %2, %0;" : "+l"(d) : "l"(a), "l"(b));
}
__device__ __forceinline__ float sum2(u64 v){
    float a, b;
    asm("mov.b64 {%0,%1}, %2;" : "=f"(a), "=f"(b) : "l"(v));
    return a + b;
}
__device__ __forceinline__ float sigm(float x){
    return __fdividef(1.0f, 1.0f + __expf(-x));
}
__device__ __forceinline__ float tanh_f(float x){
    float ax = fabsf(x);
    float e  = __expf(-2.0f * ax);
    float r  = __fdividef(1.0f - e, 1.0f + e);
    return copysignf(r, x);
}

// Computes, for this thread's NPOS positions and 2 batch elements (A,B), the
// pre-activations of TWO gates (rows at Wg1/Wg2 + jj*KP) as dot(h, W_row) + bias
// (+ Wx*x for layer 1). f32x2 packed FMAs over the K dimension.
template<bool WITH_X>
__device__ __forceinline__ void gate_pass(
    const float* __restrict__ Wg1, const float* __restrict__ Wg2,
    const float* __restrict__ bg1, const float* __restrict__ bg2,
    const float* __restrict__ wx1, const float* __restrict__ wx2,
    const float* __restrict__ hA,  const float* __restrict__ hB,
    const int* __restrict__ offs,  const int* __restrict__ jj,
    float xA, float xB,
    float* __restrict__ oA1, float* __restrict__ oB1,
    float* __restrict__ oA2, float* __restrict__ oB2)
{
    u64 accA1[NPOS], accB1[NPOS], accA2[NPOS], accB2[NPOS];
    #pragma unroll
    for (int p = 0; p < NPOS; p++){ accA1[p]=0ull; accB1[p]=0ull; accA2[p]=0ull; accB2[p]=0ull; }

    #pragma unroll
    for (int c = 0; c < NCH; c++){
        ulonglong2 hAv = *reinterpret_cast<const ulonglong2*>(hA + 4*c);
        ulonglong2 hBv = *reinterpret_cast<const ulonglong2*>(hB + 4*c);
        #pragma unroll
        for (int p = 0; p < NPOS; p++){
            ulonglong2 w1 = *reinterpret_cast<const ulonglong2*>(Wg1 + offs[p] + 4*c);
            fma2(accA1[p], w1.x, hAv.x);
            fma2(accA1[p], w1.y, hAv.y);
            fma2(accB1[p], w1.x, hBv.x);
            fma2(accB1[p], w1.y, hBv.y);
            ulonglong2 w2 = *reinterpret_cast<const ulonglong2*>(Wg2 + offs[p] + 4*c);
            fma2(accA2[p], w2.x, hAv.x);
            fma2(accA2[p], w2.y, hAv.y);
            fma2(accB2[p], w2.x, hBv.x);
            fma2(accB2[p], w2.y, hBv.y);
        }
    }

    #pragma unroll
    for (int p = 0; p < NPOS; p++){
        float b1v = bg1[jj[p]], b2v = bg2[jj[p]];
        float sA1 = sum2(accA1[p]) + b1v;
        float sB1 = sum2(accB1[p]) + b1v;
        float sA2 = sum2(accA2[p]) + b2v;
        float sB2 = sum2(accB2[p]) + b2v;
        if constexpr (WITH_X){
            float w1v = wx1[jj[p]], w2v = wx2[jj[p]];
            sA1 += w1v * xA;  sB1 += w1v * xB;
            sA2 += w2v * xA;  sB2 += w2v * xB;
        }
        oA1[p] = sA1; oB1[p] = sB1; oA2[p] = sA2; oB2[p] = sB2;
    }
}

__global__ void __launch_bounds__(TPB, 1)
lstm_pred_kernel(
    const float* __restrict__ x,
    const float* __restrict__ Wih1, const float* __restrict__ Whh1,
    const float* __restrict__ bih1, const float* __restrict__ bhh1,
    const float* __restrict__ Wih2, const float* __restrict__ Whh2,
    const float* __restrict__ bih2, const float* __restrict__ bhh2,
    const float* __restrict__ Wout, const float* __restrict__ bout,
    float* __restrict__ out)
{
    extern __shared__ float sm[];
    float* W1s  = sm;                        // [H4][KP]
    float* W2s  = W1s + H4*KP;               // [H4][KP]  (Wih2 + Whh2 combined)
    float* hS   = W2s + H4*KP;               // [BPC][KP]
    float* b1s  = hS  + BPC*KP;              // [H4]
    float* b2s  = b1s + H4;                  // [H4]
    float* wx1s = b2s + H4;                  // [H4]

    int tid = threadIdx.x;
    for (int idx = tid; idx < H4*KP; idx += TPB){
        int r = idx / KP, k = idx - r*KP;
        float w1 = 0.f, w2 = 0.f;
        if (k < Hh){
            w1 = Whh1[r*Hh + k];
            w2 = Wih2[r*Hh + k] + Whh2[r*Hh + k];
        }
        W1s[idx] = w1;
        W2s[idx] = w2;
    }
    for (int idx = tid; idx < BPC*KP; idx += TPB) hS[idx] = 0.f;
    for (int idx = tid; idx < H4; idx += TPB){
        b1s[idx]  = bih1[idx] + bhh1[idx];
        b2s[idx]  = bih2[idx] + bhh2[idx];
        wx1s[idx] = Wih1[idx];
    }
    __syncthreads();

    int grp = tid >> 3, gid = tid & 7;
    int bA = blockIdx.x * BPC + grp * 2;
    int bB = bA + 1;
    float* hA = hS + (grp*2) * KP;
    float* hB = hA + KP;

    int jj[NPOS], offs[NPOS];
    bool valp[NPOS];
    float woutp[NPOS];
    #pragma unroll
    for (int p = 0; p < NPOS; p++){
        int j = gid + 8*p;
        bool v = (j < Hh);
        valp[p]  = v;
        int jc   = v ? j : (Hh - 1);
        jj[p]    = jc;
        offs[p]  = jc * KP;
        woutp[p] = v ? Wout[j] : 0.f;
    }

    float cA[NPOS], cB[NPOS];
    #pragma unroll
    for (int p = 0; p < NPOS; p++){ cA[p] = 0.f; cB[p] = 0.f; }

    const float* xAp = x + (size_t)bA * Tt;
    const float* xBp = x + (size_t)bB * Tt;
    float* oAp = out + (size_t)bA * OTot;
    float* oBp = out + (size_t)bB * OTot;
    float bo = *bout;
    float prevA = 0.f, prevB = 0.f;
    float xnA = __ldg(xAp), xnB = __ldg(xBp);

    const float* W1_i = W1s;              const float* W1_f = W1s + Hh*KP;
    const float* W1_g = W1s + 2*Hh*KP;    const float* W1_o = W1s + 3*Hh*KP;
    const float* W2_i = W2s;              const float* W2_f = W2s + Hh*KP;
    const float* W2_g = W2s + 2*Hh*KP;    const float* W2_o = W2s + 3*Hh*KP;

    for (int t = 0; t < OTot; t++){
        float xA = (t < Tt) ? xnA : prevA;
        float xB = (t < Tt) ? xnB : prevB;
        if (t + 1 < Tt){ xnA = __ldg(xAp + t + 1); xnB = __ldg(xBp + t + 1); }

        // ---- layer 1 ----
        float giA[NPOS], giB[NPOS], gfA[NPOS], gfB[NPOS];
        gate_pass<true>(W1_i, W1_f, b1s, b1s + Hh, wx1s, wx1s + Hh,
                        hA, hB, offs, jj, xA, xB, giA, giB, gfA, gfB);
        float ggA[NPOS], ggB[NPOS], goA[NPOS], goB[NPOS];
        gate_pass<true>(W1_g, W1_o, b1s + 2*Hh, b1s + 3*Hh, wx1s + 2*Hh, wx1s + 3*Hh,
                        hA, hB, offs, jj, xA, xB, ggA, ggB, goA, goB);

        float hnA[NPOS], hnB[NPOS];
        #pragma unroll
        for (int p = 0; p < NPOS; p++){
            float iA = sigm(giA[p]), fA = sigm(gfA[p]);
            float gA = tanh_f(ggA[p]), oA = sigm(goA[p]);
            cA[p] = fA * cA[p] + iA * gA;
            hnA[p] = oA * tanh_f(cA[p]);
            float iB = sigm(giB[p]), fB = sigm(gfB[p]);
            float gB = tanh_f(ggB[p]), oB = sigm(goB[p]);
            cB[p] = fB * cB[p] + iB * gB;
            hnB[p] = oB * tanh_f(cB[p]);
        }
        __syncwarp();
        #pragma unroll
        for (int p = 0; p < NPOS; p++){
            if (valp[p]){ hA[jj[p]] = hnA[p]; hB[jj[p]] = hnB[p]; }
        }
        __syncwarp();

        // ---- layer 2 (emit): x = h = new h1, c = new c1; combined W2 ----
        gate_pass<false>(W2_i, W2_f, b2s, b2s + Hh, nullptr, nullptr,
                         hA, hB, offs, jj, 0.f, 0.f, giA, giB, gfA, gfB);
        gate_pass<false>(W2_g, W2_o, b2s + 2*Hh, b2s + 3*Hh, nullptr, nullptr,
                         hA, hB, offs, jj, 0.f, 0.f, ggA, ggB, goA, goB);

        float pA = 0.f, pB = 0.f;
        #pragma unroll
        for (int p = 0; p < NPOS; p++){
            float iA = sigm(giA[p]), fA = sigm(gfA[p]);
            float gA = tanh_f(ggA[p]), oA = sigm(goA[p]);
            float c2A = fA * cA[p] + iA * gA;
            pA += (oA * tanh_f(c2A)) * woutp[p];
            float iB = sigm(giB[p]), fB = sigm(gfB[p]);
            float gB = tanh_f(ggB[p]), oB = sigm(goB[p]);
            float c2B = fB * cB[p] + iB * gB;
            pB += (oB * tanh_f(c2B)) * woutp[p];
        }
        #pragma unroll
        for (int m = 4; m; m >>= 1){
            pA += __shfl_xor_sync(0xffffffffu, pA, m, 8);
            pB += __shfl_xor_sync(0xffffffffu, pB, m, 8);
        }
        float ovA = pA + bo, ovB = pB + bo;
        if (gid == 0){ oAp[t] = ovA; oBp[t] = ovB; }
        prevA = ovA;
        prevB = ovB;
    }
}

extern "C" void kernel_launch(void* const* d_in, const int* in_sizes, int n_in,
                              void* d_out, int out_size)
{
    const float* x    = (const float*)d_in[0];
    const float* Wih1 = (const float*)d_in[1];
    const float* Whh1 = (const float*)d_in[2];
    const float* bih1 = (const float*)d_in[3];
    const float* bhh1 = (const float*)d_in[4];
    const float* Wih2 = (const float*)d_in[5];
    const float* Whh2 = (const float*)d_in[6];
    const float* bih2 = (const float*)d_in[7];
    const float* bhh2 = (const float*)d_in[8];
    const float* Wout = (const float*)d_in[9];
    const float* bout = (const float*)d_in[10];
    float* out = (float*)d_out;

    const int smem_bytes = (2*H4*KP + BPC*KP + 3*H4) * (int)sizeof(float); // ~100.6 KB
    cudaFuncSetAttribute(lstm_pred_kernel,
                         cudaFuncAttributeMaxDynamicSharedMemorySize, smem_bytes);

    lstm_pred_kernel<<<Bt / BPC, TPB, smem_bytes>>>(
        x, Wih1, Whh1, bih1, bhh1, Wih2, Whh2, bih2, bhh2, Wout, bout, out);
}